// round 1
// baseline (speedup 1.0000x reference)
#include <cuda_runtime.h>

#define NNODES 50000
#define NEDGES 800000
#define DIN    256
#define DH     128
#define NLAB   1000

// ---------------- scratch (static device allocations; no cudaMalloc) --------
__device__ float g_ha[NNODES * DH];
__device__ float g_hb[NNODES * DH];
__device__ float g_agg[NNODES * DH];
__device__ float g_res[NNODES * DH];
__device__ int   g_cnt[NNODES];
__device__ int   g_rowptr[NNODES + 1];
__device__ int   g_cursor[NNODES];
__device__ int   g_csrc[NEDGES];
__device__ float g_csw[NEDGES];
__device__ float g_cpw[NEDGES];

// ---------------- packed f32x2 helpers (sm_10x) -----------------------------
__device__ __forceinline__ unsigned long long dup2(float x) {
    unsigned long long r;
    asm("mov.b64 %0, {%1, %1};" : "=l"(r) : "f"(x));
    return r;
}
__device__ __forceinline__ void fma2(unsigned long long& d, unsigned long long a,
                                     unsigned long long b) {
    asm("fma.rn.f32x2 %0, %1, %2, %0;" : "+l"(d) : "l"(a), "l"(b));
}
__device__ __forceinline__ void unpack2(unsigned long long v, float& lo, float& hi) {
    asm("mov.b64 {%0, %1}, %2;" : "=f"(lo), "=f"(hi) : "l"(v));
}

// ---------------- CSR build -------------------------------------------------
__global__ void zero_cnt_kernel() {
    int i = blockIdx.x * blockDim.x + threadIdx.x;
    if (i < NNODES) g_cnt[i] = 0;
}

__global__ void hist_kernel(const int* __restrict__ dst, int E) {
    int i = blockIdx.x * blockDim.x + threadIdx.x;
    if (i < E) atomicAdd(&g_cnt[dst[i]], 1);
}

// single-block exclusive scan over 50000 counts (warp-shuffle based)
__global__ void scan_kernel() {
    __shared__ int warp_sums[32];
    __shared__ int s_carry;
    const int tid = threadIdx.x;
    const int lane = tid & 31;
    const int wid = tid >> 5;
    if (tid == 0) s_carry = 0;
    __syncthreads();

    for (int base = 0; base < NNODES; base += 1024) {
        int i = base + tid;
        int v = (i < NNODES) ? g_cnt[i] : 0;
        int incl = v;
        #pragma unroll
        for (int off = 1; off < 32; off <<= 1) {
            int t = __shfl_up_sync(0xFFFFFFFFu, incl, off);
            if (lane >= off) incl += t;
        }
        if (lane == 31) warp_sums[wid] = incl;
        __syncthreads();
        if (wid == 0) {
            int ws = warp_sums[lane];
            #pragma unroll
            for (int off = 1; off < 32; off <<= 1) {
                int t = __shfl_up_sync(0xFFFFFFFFu, ws, off);
                if (lane >= off) ws += t;
            }
            warp_sums[lane] = ws;
        }
        __syncthreads();
        int warp_off = (wid == 0) ? 0 : warp_sums[wid - 1];
        int excl = s_carry + warp_off + incl - v;
        if (i < NNODES) {
            g_rowptr[i] = excl;
            g_cursor[i] = excl;
        }
        int chunk_total = warp_sums[31];
        __syncthreads();
        if (tid == 0) s_carry += chunk_total;
        __syncthreads();
    }
    if (tid == 0) g_rowptr[NNODES] = s_carry;
}

__global__ void scatter_kernel(const int* __restrict__ src, const int* __restrict__ dst,
                               const float* __restrict__ sw, const float* __restrict__ pw,
                               int E) {
    int i = blockIdx.x * blockDim.x + threadIdx.x;
    if (i < E) {
        int d = dst[i];
        int pos = atomicAdd(&g_cursor[d], 1);
        g_csrc[pos] = src[i];
        g_csw[pos]  = sw[i];
        g_cpw[pos]  = pw[i];
    }
}

// ---------------- aggregation: warp per dst node ----------------------------
// res[dst] += h[src] * self_w ; agg[dst] += h[src] * ppi_w
__global__ void aggregate_kernel(const float* __restrict__ h) {
    int warp = (blockIdx.x * blockDim.x + threadIdx.x) >> 5;
    int lane = threadIdx.x & 31;
    if (warp >= NNODES) return;
    int beg = g_rowptr[warp];
    int end = g_rowptr[warp + 1];

    float4 as = make_float4(0.f, 0.f, 0.f, 0.f);
    float4 ap = make_float4(0.f, 0.f, 0.f, 0.f);

    int e = beg;
    for (; e + 1 < end; e += 2) {
        int   s0  = g_csrc[e];
        int   s1  = g_csrc[e + 1];
        float sw0 = g_csw[e],     pw0 = g_cpw[e];
        float sw1 = g_csw[e + 1], pw1 = g_cpw[e + 1];
        float4 h0 = *reinterpret_cast<const float4*>(&h[(size_t)s0 * DH + lane * 4]);
        float4 h1 = *reinterpret_cast<const float4*>(&h[(size_t)s1 * DH + lane * 4]);
        as.x += sw0 * h0.x; as.y += sw0 * h0.y; as.z += sw0 * h0.z; as.w += sw0 * h0.w;
        ap.x += pw0 * h0.x; ap.y += pw0 * h0.y; ap.z += pw0 * h0.z; ap.w += pw0 * h0.w;
        as.x += sw1 * h1.x; as.y += sw1 * h1.y; as.z += sw1 * h1.z; as.w += sw1 * h1.w;
        ap.x += pw1 * h1.x; ap.y += pw1 * h1.y; ap.z += pw1 * h1.z; ap.w += pw1 * h1.w;
    }
    if (e < end) {
        int   s0  = g_csrc[e];
        float sw0 = g_csw[e], pw0 = g_cpw[e];
        float4 h0 = *reinterpret_cast<const float4*>(&h[(size_t)s0 * DH + lane * 4]);
        as.x += sw0 * h0.x; as.y += sw0 * h0.y; as.z += sw0 * h0.z; as.w += sw0 * h0.w;
        ap.x += pw0 * h0.x; ap.y += pw0 * h0.y; ap.z += pw0 * h0.z; ap.w += pw0 * h0.w;
    }
    *reinterpret_cast<float4*>(&g_res[(size_t)warp * DH + lane * 4]) = as;
    *reinterpret_cast<float4*>(&g_agg[(size_t)warp * DH + lane * 4]) = ap;
}

// ---------------- fp32 GEMM with packed f32x2 FMA ---------------------------
// C[M,Nc] = op(A[M,K] @ B[K,Nc] + bias)  [+ Res]
// BM=128, BN=128, BK=16, thread tile 8x8 (as 8 x 4 f32x2 pairs), 256 threads.
// Column mapping per thread: two 4-wide chunks at tx*4 and tx*4+64 (conflict-free LDS.128).
template<bool RELU, bool ADDRES>
__global__ __launch_bounds__(256)
void sgemm_kernel(const float* __restrict__ A, const float* __restrict__ B,
                  const float* __restrict__ bias, const float* __restrict__ Res,
                  float* __restrict__ C, int M, int K, int Nc) {
    __shared__ float As[16][132];   // A tile transposed [k][m], padded
    __shared__ float Bs[16][128];   // B tile [k][n]

    const int tid = threadIdx.x;
    const int tx = tid & 15;
    const int ty = tid >> 4;
    const int rowBase = blockIdx.x * 128;
    const int colBase = blockIdx.y * 128;

    const int aRow = tid >> 2;          // 0..63
    const int aCol = (tid & 3) << 2;    // 0,4,8,12
    const int bRow = tid >> 5;          // 0..7
    const int bCol = (tid & 31) << 2;   // 0..124

    unsigned long long acc[8][4];
    #pragma unroll
    for (int i = 0; i < 8; i++)
        #pragma unroll
        for (int j = 0; j < 4; j++) acc[i][j] = 0ull;

    for (int k0 = 0; k0 < K; k0 += 16) {
        // A tile: 128x16, store transposed
        #pragma unroll
        for (int p = 0; p < 2; p++) {
            int r = aRow + p * 64;
            int gr = rowBase + r;
            float4 v = make_float4(0.f, 0.f, 0.f, 0.f);
            if (gr < M)
                v = *reinterpret_cast<const float4*>(&A[(size_t)gr * K + k0 + aCol]);
            As[aCol + 0][r] = v.x;
            As[aCol + 1][r] = v.y;
            As[aCol + 2][r] = v.z;
            As[aCol + 3][r] = v.w;
        }
        // B tile: 16x128
        #pragma unroll
        for (int p = 0; p < 2; p++) {
            int r = bRow + p * 8;
            int gc = colBase + bCol;
            float4 v = make_float4(0.f, 0.f, 0.f, 0.f);
            if (gc < Nc)
                v = *reinterpret_cast<const float4*>(&B[(size_t)(k0 + r) * Nc + gc]);
            *reinterpret_cast<float4*>(&Bs[r][bCol]) = v;
        }
        __syncthreads();

        #pragma unroll
        for (int kk = 0; kk < 16; kk++) {
            float4 a0 = *reinterpret_cast<const float4*>(&As[kk][ty * 8]);
            float4 a1 = *reinterpret_cast<const float4*>(&As[kk][ty * 8 + 4]);
            ulonglong2 bl0 = *reinterpret_cast<const ulonglong2*>(&Bs[kk][tx * 4]);
            ulonglong2 bl1 = *reinterpret_cast<const ulonglong2*>(&Bs[kk][tx * 4 + 64]);
            unsigned long long b2[4] = {bl0.x, bl0.y, bl1.x, bl1.y};
            unsigned long long a2[8];
            a2[0] = dup2(a0.x); a2[1] = dup2(a0.y); a2[2] = dup2(a0.z); a2[3] = dup2(a0.w);
            a2[4] = dup2(a1.x); a2[5] = dup2(a1.y); a2[6] = dup2(a1.z); a2[7] = dup2(a1.w);
            #pragma unroll
            for (int i = 0; i < 8; i++)
                #pragma unroll
                for (int j = 0; j < 4; j++)
                    fma2(acc[i][j], a2[i], b2[j]);
        }
        __syncthreads();
    }

    // epilogue: cols for pair j: colBase + (j>>1)*64 + tx*4 + (j&1)*2
    #pragma unroll
    for (int i = 0; i < 8; i++) {
        int gr = rowBase + ty * 8 + i;
        if (gr >= M) continue;
        #pragma unroll
        for (int j = 0; j < 4; j++) {
            float v0, v1;
            unpack2(acc[i][j], v0, v1);
            int c0 = colBase + ((j >> 1) << 6) + tx * 4 + ((j & 1) << 1);
            if (c0 < Nc) {
                float r0 = v0 + bias[c0];
                if (RELU)   r0 = fmaxf(r0, 0.f);
                if (ADDRES) r0 += Res[(size_t)gr * Nc + c0];
                C[(size_t)gr * Nc + c0] = r0;
            }
            if (c0 + 1 < Nc) {
                float r1 = v1 + bias[c0 + 1];
                if (RELU)   r1 = fmaxf(r1, 0.f);
                if (ADDRES) r1 += Res[(size_t)gr * Nc + c0 + 1];
                C[(size_t)gr * Nc + c0 + 1] = r1;
            }
        }
    }
}

// ---------------- launch ----------------------------------------------------
extern "C" void kernel_launch(void* const* d_in, const int* in_sizes, int n_in,
                              void* d_out, int out_size) {
    const float* x      = (const float*)d_in[0];
    const int*   src    = (const int*)  d_in[1];
    const int*   dst    = (const int*)  d_in[2];
    const float* self_w = (const float*)d_in[3];
    const float* ppi_w  = (const float*)d_in[4];
    const float* W_in   = (const float*)d_in[5];
    const float* b_in   = (const float*)d_in[6];
    const float* W1     = (const float*)d_in[7];
    const float* b1     = (const float*)d_in[8];
    const float* W2     = (const float*)d_in[9];
    const float* b2     = (const float*)d_in[10];
    const float* W_out  = (const float*)d_in[11];
    const float* b_out  = (const float*)d_in[12];
    float* out = (float*)d_out;
    const int E = in_sizes[1];

    float *ha, *hb, *agg, *res;
    cudaGetSymbolAddress((void**)&ha,  g_ha);
    cudaGetSymbolAddress((void**)&hb,  g_hb);
    cudaGetSymbolAddress((void**)&agg, g_agg);
    cudaGetSymbolAddress((void**)&res, g_res);

    // CSR by dst (rebuilt every call; no caching)
    zero_cnt_kernel<<<(NNODES + 255) / 256, 256>>>();
    hist_kernel<<<(E + 255) / 256, 256>>>(dst, E);
    scan_kernel<<<1, 1024>>>();
    scatter_kernel<<<(E + 255) / 256, 256>>>(src, dst, self_w, ppi_w, E);

    const dim3 blk(256);
    const dim3 g_n128((NNODES + 127) / 128, 1);
    const dim3 g_out((NNODES + 127) / 128, (NLAB + 127) / 128);
    const int agg_blocks = (NNODES * 32 + 255) / 256;

    // h = relu(x @ W_in + b_in)
    sgemm_kernel<true, false><<<g_n128, blk>>>(x, W_in, b_in, nullptr, ha, NNODES, DIN, DH);

    // layer 1
    aggregate_kernel<<<agg_blocks, blk>>>(ha);
    sgemm_kernel<true, true><<<g_n128, blk>>>(agg, W1, b1, res, hb, NNODES, DH, DH);

    // layer 2
    aggregate_kernel<<<agg_blocks, blk>>>(hb);
    sgemm_kernel<true, true><<<g_n128, blk>>>(agg, W2, b2, res, ha, NNODES, DH, DH);

    // out = h @ W_out + b_out
    sgemm_kernel<false, false><<<g_out, blk>>>(ha, W_out, b_out, nullptr, out, NNODES, DH, NLAB);
}

// round 3
// speedup vs baseline: 1.0518x; 1.0518x over previous
#include <cuda_runtime.h>
#include <cuda_bf16.h>
#include <cstdint>

#define NNODES 50000
#define NEDGES 800000
#define DIN    256
#define DH     128
#define NLAB   1000

// ---------------- scratch (static device allocations; no cudaMalloc) --------
__device__ float g_ha[NNODES * DH];
__device__ float g_hb[NNODES * DH];
__device__ float g_agg[NNODES * DH];
__device__ float g_res[NNODES * DH];
__device__ int   g_cnt[NNODES];
__device__ int   g_rowptr[NNODES + 1];
__device__ int   g_cursor[NNODES];
__device__ int   g_csrc[NEDGES];
__device__ float g_csw[NEDGES];
__device__ float g_cpw[NEDGES];

// ---------------- helpers ----------------------------------------------------
__device__ __forceinline__ uint32_t smem_u32(const void* p) {
    uint32_t a;
    asm("{ .reg .u64 t; cvta.to.shared.u64 t, %1; cvt.u32.u64 %0, t; }" : "=r"(a) : "l"(p));
    return a;
}
__device__ __forceinline__ uint32_t pack_bf2(float e0, float e1) {
    // low half = bf16(e0), high half = bf16(e1)
    uint32_t r;
    asm("cvt.rn.satfinite.bf16x2.f32 %0, %1, %2;" : "=r"(r) : "f"(e1), "f"(e0));
    return r;
}

#define LDSM4(r, addr)                                                          \
    asm volatile("ldmatrix.sync.aligned.m8n8.x4.shared.b16 {%0,%1,%2,%3}, [%4];"\
        : "=r"((r)[0]), "=r"((r)[1]), "=r"((r)[2]), "=r"((r)[3]) : "r"(addr))
#define LDSM4T(r, addr)                                                         \
    asm volatile("ldmatrix.sync.aligned.m8n8.x4.trans.shared.b16 {%0,%1,%2,%3}, [%4];"\
        : "=r"((r)[0]), "=r"((r)[1]), "=r"((r)[2]), "=r"((r)[3]) : "r"(addr))
#define MMA16816(d, a, b)                                                       \
    asm volatile("mma.sync.aligned.m16n8k16.row.col.f32.bf16.bf16.f32 "         \
        "{%0,%1,%2,%3}, {%4,%5,%6,%7}, {%8,%9}, {%0,%1,%2,%3};"                 \
        : "+f"((d)[0]), "+f"((d)[1]), "+f"((d)[2]), "+f"((d)[3])                \
        : "r"((a)[0]), "r"((a)[1]), "r"((a)[2]), "r"((a)[3]),                   \
          "r"((b)[0]), "r"((b)[1]))

// ---------------- CSR build -------------------------------------------------
__global__ void zero_cnt_kernel() {
    int i = blockIdx.x * blockDim.x + threadIdx.x;
    if (i < NNODES) g_cnt[i] = 0;
}
__global__ void hist_kernel(const int* __restrict__ dst, int E) {
    int i = blockIdx.x * blockDim.x + threadIdx.x;
    if (i < E) atomicAdd(&g_cnt[dst[i]], 1);
}
__global__ void scan_kernel() {
    __shared__ int warp_sums[32];
    __shared__ int s_carry;
    const int tid = threadIdx.x;
    const int lane = tid & 31;
    const int wid = tid >> 5;
    if (tid == 0) s_carry = 0;
    __syncthreads();
    for (int base = 0; base < NNODES; base += 1024) {
        int i = base + tid;
        int v = (i < NNODES) ? g_cnt[i] : 0;
        int incl = v;
        #pragma unroll
        for (int off = 1; off < 32; off <<= 1) {
            int t = __shfl_up_sync(0xFFFFFFFFu, incl, off);
            if (lane >= off) incl += t;
        }
        if (lane == 31) warp_sums[wid] = incl;
        __syncthreads();
        if (wid == 0) {
            int ws = warp_sums[lane];
            #pragma unroll
            for (int off = 1; off < 32; off <<= 1) {
                int t = __shfl_up_sync(0xFFFFFFFFu, ws, off);
                if (lane >= off) ws += t;
            }
            warp_sums[lane] = ws;
        }
        __syncthreads();
        int warp_off = (wid == 0) ? 0 : warp_sums[wid - 1];
        int excl = s_carry + warp_off + incl - v;
        if (i < NNODES) { g_rowptr[i] = excl; g_cursor[i] = excl; }
        int chunk_total = warp_sums[31];
        __syncthreads();
        if (tid == 0) s_carry += chunk_total;
        __syncthreads();
    }
    if (tid == 0) g_rowptr[NNODES] = s_carry;
}
__global__ void scatter_kernel(const int* __restrict__ src, const int* __restrict__ dst,
                               const float* __restrict__ sw, const float* __restrict__ pw,
                               int E) {
    int i = blockIdx.x * blockDim.x + threadIdx.x;
    if (i < E) {
        int d = dst[i];
        int pos = atomicAdd(&g_cursor[d], 1);
        g_csrc[pos] = src[i];
        g_csw[pos]  = sw[i];
        g_cpw[pos]  = pw[i];
    }
}

// ---------------- aggregation: warp per dst node ----------------------------
__global__ void aggregate_kernel(const float* __restrict__ h) {
    int warp = (blockIdx.x * blockDim.x + threadIdx.x) >> 5;
    int lane = threadIdx.x & 31;
    if (warp >= NNODES) return;
    int beg = g_rowptr[warp];
    int end = g_rowptr[warp + 1];
    float4 as = make_float4(0.f, 0.f, 0.f, 0.f);
    float4 ap = make_float4(0.f, 0.f, 0.f, 0.f);
    int e = beg;
    for (; e + 1 < end; e += 2) {
        int   s0 = g_csrc[e], s1 = g_csrc[e + 1];
        float sw0 = g_csw[e], pw0 = g_cpw[e];
        float sw1 = g_csw[e + 1], pw1 = g_cpw[e + 1];
        float4 h0 = *reinterpret_cast<const float4*>(&h[(size_t)s0 * DH + lane * 4]);
        float4 h1 = *reinterpret_cast<const float4*>(&h[(size_t)s1 * DH + lane * 4]);
        as.x += sw0 * h0.x; as.y += sw0 * h0.y; as.z += sw0 * h0.z; as.w += sw0 * h0.w;
        ap.x += pw0 * h0.x; ap.y += pw0 * h0.y; ap.z += pw0 * h0.z; ap.w += pw0 * h0.w;
        as.x += sw1 * h1.x; as.y += sw1 * h1.y; as.z += sw1 * h1.z; as.w += sw1 * h1.w;
        ap.x += pw1 * h1.x; ap.y += pw1 * h1.y; ap.z += pw1 * h1.z; ap.w += pw1 * h1.w;
    }
    if (e < end) {
        int   s0 = g_csrc[e];
        float sw0 = g_csw[e], pw0 = g_cpw[e];
        float4 h0 = *reinterpret_cast<const float4*>(&h[(size_t)s0 * DH + lane * 4]);
        as.x += sw0 * h0.x; as.y += sw0 * h0.y; as.z += sw0 * h0.z; as.w += sw0 * h0.w;
        ap.x += pw0 * h0.x; ap.y += pw0 * h0.y; ap.z += pw0 * h0.z; ap.w += pw0 * h0.w;
    }
    *reinterpret_cast<float4*>(&g_res[(size_t)warp * DH + lane * 4]) = as;
    *reinterpret_cast<float4*>(&g_agg[(size_t)warp * DH + lane * 4]) = ap;
}

// ---------------- bf16-split GEMM on HMMA (mma.sync, baseline PTX) ----------
// C[M,Nc] = op(A @ B + bias) [+Res], fp32 in/out.
// fp32 -> (hi,lo) bf16; C = AhiBhi + AhiBlo + AloBhi with fp32 accum.
// Block 128x128, BK=32, 8 warps (warp tile 32M x 64N), m16n8k16 HMMA.
// SMEM strides: A 80B/row, B 272B/row -> ldmatrix conflict-free.
#define SA_STRIDE 80
#define SB_STRIDE 272
#define OFF_A_HI 0
#define OFF_A_LO 10240
#define OFF_B_HI 20480
#define OFF_B_LO 29184
#define OFF_BIAS 37888
#define SM_TOTAL 38400

template<bool RELU, bool ADDRES>
__global__ __launch_bounds__(256, 1)
void mma_gemm(const float* __restrict__ A, const float* __restrict__ B,
              const float* __restrict__ bias, const float* __restrict__ Res,
              float* __restrict__ C, int M, int K, int Nc) {
    __shared__ __align__(16) char smem[SM_TOTAL];
    const uint32_t sb = smem_u32(smem);
    const int tid  = threadIdx.x;
    const int wid  = tid >> 5;
    const int lane = tid & 31;
    const int rowBase = blockIdx.x * 128;
    const int colBase = blockIdx.y * 128;
    const int wm = (wid >> 1) * 32;   // warp row offset in tile
    const int wn = (wid & 1) * 64;    // warp col offset in tile
    float* bias_s = reinterpret_cast<float*>(smem + OFF_BIAS);

    if (tid < 128) {
        int gc = colBase + tid;
        bias_s[tid] = (gc < Nc) ? bias[gc] : 0.f;
    }

    float acc[2][8][4];
    #pragma unroll
    for (int mt = 0; mt < 2; mt++)
        #pragma unroll
        for (int nt = 0; nt < 8; nt++)
            #pragma unroll
            for (int q = 0; q < 4; q++) acc[mt][nt][q] = 0.f;

    for (int k0 = 0; k0 < K; k0 += 32) {
        // ---- fill A tile: 128 rows x 32 k (hi/lo bf16) ----
        #pragma unroll
        for (int it = tid; it < 1024; it += 256) {
            int r  = it >> 3;
            int kq = (it & 7) << 2;
            int gr = rowBase + r;
            float4 v = make_float4(0.f, 0.f, 0.f, 0.f);
            if (gr < M) v = *reinterpret_cast<const float4*>(&A[(size_t)gr * K + k0 + kq]);
            uint32_t hp01 = pack_bf2(v.x, v.y);
            uint32_t hp23 = pack_bf2(v.z, v.w);
            float hx = __uint_as_float(hp01 << 16);
            float hy = __uint_as_float(hp01 & 0xFFFF0000u);
            float hz = __uint_as_float(hp23 << 16);
            float hw = __uint_as_float(hp23 & 0xFFFF0000u);
            uint32_t lp01 = pack_bf2(v.x - hx, v.y - hy);
            uint32_t lp23 = pack_bf2(v.z - hz, v.w - hw);
            int ad = r * SA_STRIDE + kq * 2;
            *reinterpret_cast<uint2*>(smem + OFF_A_HI + ad) = make_uint2(hp01, hp23);
            *reinterpret_cast<uint2*>(smem + OFF_A_LO + ad) = make_uint2(lp01, lp23);
        }
        // ---- fill B tile: 32 k x 128 n (hi/lo bf16) ----
        #pragma unroll
        for (int it = tid; it < 1024; it += 256) {
            int kr = it >> 5;
            int nq = (it & 31) << 2;
            int gc = colBase + nq;
            const float* Brow = &B[(size_t)(k0 + kr) * Nc];
            float4 v;
            if (gc + 3 < Nc) {
                v = *reinterpret_cast<const float4*>(&Brow[gc]);
            } else {
                v.x = (gc     < Nc) ? Brow[gc]     : 0.f;
                v.y = (gc + 1 < Nc) ? Brow[gc + 1] : 0.f;
                v.z = (gc + 2 < Nc) ? Brow[gc + 2] : 0.f;
                v.w = (gc + 3 < Nc) ? Brow[gc + 3] : 0.f;
            }
            uint32_t hp01 = pack_bf2(v.x, v.y);
            uint32_t hp23 = pack_bf2(v.z, v.w);
            float hx = __uint_as_float(hp01 << 16);
            float hy = __uint_as_float(hp01 & 0xFFFF0000u);
            float hz = __uint_as_float(hp23 << 16);
            float hw = __uint_as_float(hp23 & 0xFFFF0000u);
            uint32_t lp01 = pack_bf2(v.x - hx, v.y - hy);
            uint32_t lp23 = pack_bf2(v.z - hz, v.w - hw);
            int ad = kr * SB_STRIDE + nq * 2;
            *reinterpret_cast<uint2*>(smem + OFF_B_HI + ad) = make_uint2(hp01, hp23);
            *reinterpret_cast<uint2*>(smem + OFF_B_LO + ad) = make_uint2(lp01, lp23);
        }
        __syncthreads();

        #pragma unroll
        for (int kk = 0; kk < 32; kk += 16) {
            // A fragments (hi & lo) for 2 m16 tiles
            uint32_t ahi[2][4], alo[2][4];
            #pragma unroll
            for (int mt = 0; mt < 2; mt++) {
                int row = wm + mt * 16 + (lane & 15);
                int col = kk + ((lane >> 4) << 3);
                uint32_t aadr = sb + OFF_A_HI + row * SA_STRIDE + col * 2;
                LDSM4(ahi[mt], aadr);
                LDSM4(alo[mt], aadr + (OFF_A_LO - OFF_A_HI));
            }
            // B fragments in groups of 2 n8 tiles
            #pragma unroll
            for (int g = 0; g < 4; g++) {
                int krow = kk + ((lane >> 3) & 1) * 8 + (lane & 7);
                int ncol = wn + g * 16 + ((lane >> 4) << 3);
                uint32_t badr = sb + OFF_B_HI + krow * SB_STRIDE + ncol * 2;
                uint32_t bh[4], bl[4];
                LDSM4T(bh, badr);
                LDSM4T(bl, badr + (OFF_B_LO - OFF_B_HI));
                #pragma unroll
                for (int half = 0; half < 2; half++) {
                    int nt = g * 2 + half;
                    #pragma unroll
                    for (int mt = 0; mt < 2; mt++) {
                        MMA16816(acc[mt][nt], ahi[mt], bh + 2 * half);
                        MMA16816(acc[mt][nt], ahi[mt], bl + 2 * half);
                        MMA16816(acc[mt][nt], alo[mt], bh + 2 * half);
                    }
                }
            }
        }
        __syncthreads();
    }

    // ---- epilogue: direct global stores (32B-sector friendly float2) ----
    const int g4 = lane >> 2;
    const int t4 = lane & 3;
    #pragma unroll
    for (int mt = 0; mt < 2; mt++) {
        #pragma unroll
        for (int half = 0; half < 2; half++) {
            int gr = rowBase + wm + mt * 16 + g4 + half * 8;
            if (gr >= M) continue;
            #pragma unroll
            for (int nt = 0; nt < 8; nt++) {
                int cl = wn + nt * 8 + t4 * 2;
                int gc = colBase + cl;
                float v0 = acc[mt][nt][half * 2]     + bias_s[cl];
                float v1 = acc[mt][nt][half * 2 + 1] + bias_s[cl + 1];
                if (RELU) { v0 = fmaxf(v0, 0.f); v1 = fmaxf(v1, 0.f); }
                if (gc + 1 < Nc) {
                    if (ADDRES) {
                        float2 rr = *reinterpret_cast<const float2*>(&Res[(size_t)gr * Nc + gc]);
                        v0 += rr.x; v1 += rr.y;
                    }
                    *reinterpret_cast<float2*>(&C[(size_t)gr * Nc + gc]) = make_float2(v0, v1);
                } else if (gc < Nc) {
                    if (ADDRES) v0 += Res[(size_t)gr * Nc + gc];
                    C[(size_t)gr * Nc + gc] = v0;
                }
            }
        }
    }
}

// ---------------- launch ----------------------------------------------------
extern "C" void kernel_launch(void* const* d_in, const int* in_sizes, int n_in,
                              void* d_out, int out_size) {
    const float* x      = (const float*)d_in[0];
    const int*   src    = (const int*)  d_in[1];
    const int*   dst    = (const int*)  d_in[2];
    const float* self_w = (const float*)d_in[3];
    const float* ppi_w  = (const float*)d_in[4];
    const float* W_in   = (const float*)d_in[5];
    const float* b_in   = (const float*)d_in[6];
    const float* W1     = (const float*)d_in[7];
    const float* b1     = (const float*)d_in[8];
    const float* W2     = (const float*)d_in[9];
    const float* b2     = (const float*)d_in[10];
    const float* W_out  = (const float*)d_in[11];
    const float* b_out  = (const float*)d_in[12];
    float* out = (float*)d_out;
    const int E = in_sizes[1];

    float *ha, *hb, *agg, *res;
    cudaGetSymbolAddress((void**)&ha,  g_ha);
    cudaGetSymbolAddress((void**)&hb,  g_hb);
    cudaGetSymbolAddress((void**)&agg, g_agg);
    cudaGetSymbolAddress((void**)&res, g_res);

    // CSR by dst (rebuilt every call)
    zero_cnt_kernel<<<(NNODES + 255) / 256, 256>>>();
    hist_kernel<<<(E + 255) / 256, 256>>>(dst, E);
    scan_kernel<<<1, 1024>>>();
    scatter_kernel<<<(E + 255) / 256, 256>>>(src, dst, self_w, ppi_w, E);

    const dim3 blk(256);
    const dim3 g_h((NNODES + 127) / 128, 1);
    const dim3 g_o((NNODES + 127) / 128, (NLAB + 127) / 128);
    const int agg_blocks = (NNODES * 32 + 255) / 256;

    // h = relu(x @ W_in + b_in)
    mma_gemm<true, false><<<g_h, blk>>>(x, W_in, b_in, nullptr, ha, NNODES, DIN, DH);
    // layer 1
    aggregate_kernel<<<agg_blocks, blk>>>(ha);
    mma_gemm<true, true><<<g_h, blk>>>(agg, W1, b1, res, hb, NNODES, DH, DH);
    // layer 2
    aggregate_kernel<<<agg_blocks, blk>>>(hb);
    mma_gemm<true, true><<<g_h, blk>>>(agg, W2, b2, res, ha, NNODES, DH, DH);
    // out = h @ W_out + b_out
    mma_gemm<false, false><<<g_o, blk>>>(ha, W_out, b_out, nullptr, out, NNODES, DH, NLAB);
}

// round 4
// speedup vs baseline: 1.4242x; 1.3541x over previous
#include <cuda_runtime.h>
#include <cuda_bf16.h>
#include <cstdint>

#define NNODES 50000
#define NEDGES 800000
#define DIN    256
#define DH     128
#define NLAB   1000
#define NSCANB 196   // ceil(50000/256)

// ---------------- scratch (static device allocations; no cudaMalloc) --------
__device__ float g_ha[NNODES * DH];
__device__ float g_hb[NNODES * DH];
__device__ float g_agg[NNODES * DH];
__device__ float g_res[NNODES * DH];
__device__ int   g_cnt[NNODES];          // zero-init; left zero after each call
__device__ int   g_rowptr[NNODES + 1];
__device__ int   g_cursor[NNODES];
__device__ int   g_bsum[NSCANB];
__device__ int   g_csrc[NEDGES];
__device__ float g_csw[NEDGES];
__device__ float g_cpw[NEDGES];

// ---------------- helpers ----------------------------------------------------
__device__ __forceinline__ uint32_t smem_u32(const void* p) {
    uint32_t a;
    asm("{ .reg .u64 t; cvta.to.shared.u64 t, %1; cvt.u32.u64 %0, t; }" : "=r"(a) : "l"(p));
    return a;
}
__device__ __forceinline__ uint32_t pack_bf2(float e0, float e1) {
    // low half = bf16(e0), high half = bf16(e1)
    uint32_t r;
    asm("cvt.rn.satfinite.bf16x2.f32 %0, %1, %2;" : "=r"(r) : "f"(e1), "f"(e0));
    return r;
}

#define LDSM4(r, addr)                                                          \
    asm volatile("ldmatrix.sync.aligned.m8n8.x4.shared.b16 {%0,%1,%2,%3}, [%4];"\
        : "=r"((r)[0]), "=r"((r)[1]), "=r"((r)[2]), "=r"((r)[3]) : "r"(addr))
#define LDSM4T(r, addr)                                                         \
    asm volatile("ldmatrix.sync.aligned.m8n8.x4.trans.shared.b16 {%0,%1,%2,%3}, [%4];"\
        : "=r"((r)[0]), "=r"((r)[1]), "=r"((r)[2]), "=r"((r)[3]) : "r"(addr))
#define MMA16816(d, a, b)                                                       \
    asm volatile("mma.sync.aligned.m16n8k16.row.col.f32.bf16.bf16.f32 "         \
        "{%0,%1,%2,%3}, {%4,%5,%6,%7}, {%8,%9}, {%0,%1,%2,%3};"                 \
        : "+f"((d)[0]), "+f"((d)[1]), "+f"((d)[2]), "+f"((d)[3])                \
        : "r"((a)[0]), "r"((a)[1]), "r"((a)[2]), "r"((a)[3]),                   \
          "r"((b)[0]), "r"((b)[1]))

// ---------------- CSR build -------------------------------------------------
__global__ void hist_kernel(const int* __restrict__ dst, int E) {
    int i = blockIdx.x * blockDim.x + threadIdx.x;
    if (i < E) atomicAdd(&g_cnt[dst[i]], 1);
}

// phase A: per-block sums of g_cnt
__global__ void scanA_kernel() {
    __shared__ int wsum[8];
    int i = blockIdx.x * 256 + threadIdx.x;
    int lane = threadIdx.x & 31, wid = threadIdx.x >> 5;
    int v = (i < NNODES) ? g_cnt[i] : 0;
    #pragma unroll
    for (int off = 16; off > 0; off >>= 1) v += __shfl_down_sync(0xFFFFFFFFu, v, off);
    if (lane == 0) wsum[wid] = v;
    __syncthreads();
    if (threadIdx.x == 0) {
        int s = 0;
        #pragma unroll
        for (int w = 0; w < 8; w++) s += wsum[w];
        g_bsum[blockIdx.x] = s;
    }
}

// phase B: 1-block exclusive scan of NSCANB block sums
__global__ void scanB_kernel() {
    __shared__ int wsc[8];
    int t = threadIdx.x;
    int lane = t & 31, wid = t >> 5;
    int v = (t < NSCANB) ? g_bsum[t] : 0;
    int incl = v;
    #pragma unroll
    for (int off = 1; off < 32; off <<= 1) {
        int u = __shfl_up_sync(0xFFFFFFFFu, incl, off);
        if (lane >= off) incl += u;
    }
    if (lane == 31) wsc[wid] = incl;
    __syncthreads();
    if (wid == 0) {
        int ws = (lane < 8) ? wsc[lane] : 0;
        #pragma unroll
        for (int off = 1; off < 8; off <<= 1) {
            int u = __shfl_up_sync(0xFFFFFFFFu, ws, off);
            if (lane >= off) ws += u;
        }
        if (lane < 8) wsc[lane] = ws;
    }
    __syncthreads();
    int excl = incl - v + (wid ? wsc[wid - 1] : 0);
    if (t < NSCANB) g_bsum[t] = excl;
    if (t == 255) g_rowptr[NNODES] = excl + v;   // grand total
}

// phase C: per-block exclusive scan + block offset -> rowptr/cursor; reset cnt
__global__ void scanC_kernel() {
    __shared__ int wsc[8];
    int i = blockIdx.x * 256 + threadIdx.x;
    int t = threadIdx.x, lane = t & 31, wid = t >> 5;
    int v = (i < NNODES) ? g_cnt[i] : 0;
    int incl = v;
    #pragma unroll
    for (int off = 1; off < 32; off <<= 1) {
        int u = __shfl_up_sync(0xFFFFFFFFu, incl, off);
        if (lane >= off) incl += u;
    }
    if (lane == 31) wsc[wid] = incl;
    __syncthreads();
    if (wid == 0) {
        int ws = (lane < 8) ? wsc[lane] : 0;
        #pragma unroll
        for (int off = 1; off < 8; off <<= 1) {
            int u = __shfl_up_sync(0xFFFFFFFFu, ws, off);
            if (lane >= off) ws += u;
        }
        if (lane < 8) wsc[lane] = ws;
    }
    __syncthreads();
    int excl = incl - v + (wid ? wsc[wid - 1] : 0) + g_bsum[blockIdx.x];
    if (i < NNODES) {
        g_rowptr[i] = excl;
        g_cursor[i] = excl;
        g_cnt[i] = 0;                 // leave zero for next call (deterministic)
    }
}

__global__ void scatter_kernel(const int* __restrict__ src, const int* __restrict__ dst,
                               const float* __restrict__ sw, const float* __restrict__ pw,
                               int E) {
    int i = blockIdx.x * blockDim.x + threadIdx.x;
    if (i < E) {
        int d = dst[i];
        int pos = atomicAdd(&g_cursor[d], 1);
        g_csrc[pos] = src[i];
        g_csw[pos]  = sw[i];
        g_cpw[pos]  = pw[i];
    }
}

// ---------------- aggregation: warp per dst node ----------------------------
__global__ void aggregate_kernel(const float* __restrict__ h) {
    int warp = (blockIdx.x * blockDim.x + threadIdx.x) >> 5;
    int lane = threadIdx.x & 31;
    if (warp >= NNODES) return;
    int beg = g_rowptr[warp];
    int end = g_rowptr[warp + 1];
    float4 as = make_float4(0.f, 0.f, 0.f, 0.f);
    float4 ap = make_float4(0.f, 0.f, 0.f, 0.f);
    int e = beg;
    for (; e + 1 < end; e += 2) {
        int   s0 = g_csrc[e], s1 = g_csrc[e + 1];
        float sw0 = g_csw[e], pw0 = g_cpw[e];
        float sw1 = g_csw[e + 1], pw1 = g_cpw[e + 1];
        float4 h0 = *reinterpret_cast<const float4*>(&h[(size_t)s0 * DH + lane * 4]);
        float4 h1 = *reinterpret_cast<const float4*>(&h[(size_t)s1 * DH + lane * 4]);
        as.x += sw0 * h0.x; as.y += sw0 * h0.y; as.z += sw0 * h0.z; as.w += sw0 * h0.w;
        ap.x += pw0 * h0.x; ap.y += pw0 * h0.y; ap.z += pw0 * h0.z; ap.w += pw0 * h0.w;
        as.x += sw1 * h1.x; as.y += sw1 * h1.y; as.z += sw1 * h1.z; as.w += sw1 * h1.w;
        ap.x += pw1 * h1.x; ap.y += pw1 * h1.y; ap.z += pw1 * h1.z; ap.w += pw1 * h1.w;
    }
    if (e < end) {
        int   s0 = g_csrc[e];
        float sw0 = g_csw[e], pw0 = g_cpw[e];
        float4 h0 = *reinterpret_cast<const float4*>(&h[(size_t)s0 * DH + lane * 4]);
        as.x += sw0 * h0.x; as.y += sw0 * h0.y; as.z += sw0 * h0.z; as.w += sw0 * h0.w;
        ap.x += pw0 * h0.x; ap.y += pw0 * h0.y; ap.z += pw0 * h0.z; ap.w += pw0 * h0.w;
    }
    *reinterpret_cast<float4*>(&g_res[(size_t)warp * DH + lane * 4]) = as;
    *reinterpret_cast<float4*>(&g_agg[(size_t)warp * DH + lane * 4]) = ap;
}

// ---------------- bf16-split GEMM on HMMA, register-prefetch pipelined ------
// C[M,Nc] = op(A @ B + bias) [+Res], fp32 in/out.
// fp32 -> (hi,lo) bf16; C = AhiBhi + AhiBlo + AloBhi with fp32 accum.
// Block 128x128, BK=32, 8 warps (warp tile 32M x 64N), m16n8k16 HMMA.
// Next chunk's global loads are issued before the HMMA burst (latency hidden).
#define SA_STRIDE 80
#define SB_STRIDE 272
#define OFF_A_HI 0
#define OFF_A_LO 10240
#define OFF_B_HI 20480
#define OFF_B_LO 29184
#define OFF_BIAS 37888
#define SM_TOTAL 38400

template<bool RELU, bool ADDRES>
__global__ __launch_bounds__(256)
void mma_gemm(const float* __restrict__ A, const float* __restrict__ B,
              const float* __restrict__ bias, const float* __restrict__ Res,
              float* __restrict__ C, int M, int K, int Nc) {
    __shared__ __align__(16) char smem[SM_TOTAL];
    const uint32_t sb = smem_u32(smem);
    const int tid  = threadIdx.x;
    const int wid  = tid >> 5;
    const int lane = tid & 31;
    const int rowBase = blockIdx.x * 128;
    const int colBase = blockIdx.y * 128;
    const int wm = (wid >> 1) * 32;
    const int wn = (wid & 1) * 64;
    float* bias_s = reinterpret_cast<float*>(smem + OFF_BIAS);

    if (tid < 128) {
        int gc = colBase + tid;
        bias_s[tid] = (gc < Nc) ? bias[gc] : 0.f;
    }

    // prefetch register staging
    float4 pa[4], pb[4];
    const int aR  = tid >> 3;           // 0..31 (row group base; +32*u)
    const int aKq = (tid & 7) << 2;     // k offset 0..28
    const int bKr = tid >> 6;           // 0..3   (k row base; +4*u... see below)
    const int bNq = (tid & 63) << 1;    // wrong width; recompute below

    auto loadA = [&](int k0) {
        #pragma unroll
        for (int u = 0; u < 4; u++) {
            int it = tid + u * 256;          // 1024 items: r=it>>3, kq=(it&7)*4
            int r  = it >> 3;
            int kq = (it & 7) << 2;
            int gr = rowBase + r;
            pa[u] = (gr < M) ? *reinterpret_cast<const float4*>(&A[(size_t)gr * K + k0 + kq])
                             : make_float4(0.f, 0.f, 0.f, 0.f);
        }
    };
    auto loadB = [&](int k0) {
        #pragma unroll
        for (int u = 0; u < 4; u++) {
            int it = tid + u * 256;          // 1024 items: kr=it>>5, nq=(it&31)*4
            int kr = it >> 5;
            int nq = (it & 31) << 2;
            int gc = colBase + nq;
            const float* Brow = &B[(size_t)(k0 + kr) * Nc];
            float4 v;
            if (gc + 3 < Nc) {
                v = *reinterpret_cast<const float4*>(&Brow[gc]);
            } else {
                v.x = (gc     < Nc) ? Brow[gc]     : 0.f;
                v.y = (gc + 1 < Nc) ? Brow[gc + 1] : 0.f;
                v.z = (gc + 2 < Nc) ? Brow[gc + 2] : 0.f;
                v.w = (gc + 3 < Nc) ? Brow[gc + 3] : 0.f;
            }
            pb[u] = v;
        }
    };
    auto storeAB = [&]() {
        #pragma unroll
        for (int u = 0; u < 4; u++) {
            int it = tid + u * 256;
            int r  = it >> 3;
            int kq = (it & 7) << 2;
            float4 v = pa[u];
            uint32_t hp01 = pack_bf2(v.x, v.y);
            uint32_t hp23 = pack_bf2(v.z, v.w);
            float hx = __uint_as_float(hp01 << 16);
            float hy = __uint_as_float(hp01 & 0xFFFF0000u);
            float hz = __uint_as_float(hp23 << 16);
            float hw = __uint_as_float(hp23 & 0xFFFF0000u);
            uint32_t lp01 = pack_bf2(v.x - hx, v.y - hy);
            uint32_t lp23 = pack_bf2(v.z - hz, v.w - hw);
            int ad = r * SA_STRIDE + kq * 2;
            *reinterpret_cast<uint2*>(smem + OFF_A_HI + ad) = make_uint2(hp01, hp23);
            *reinterpret_cast<uint2*>(smem + OFF_A_LO + ad) = make_uint2(lp01, lp23);
        }
        #pragma unroll
        for (int u = 0; u < 4; u++) {
            int it = tid + u * 256;
            int kr = it >> 5;
            int nq = (it & 31) << 2;
            float4 v = pb[u];
            uint32_t hp01 = pack_bf2(v.x, v.y);
            uint32_t hp23 = pack_bf2(v.z, v.w);
            float hx = __uint_as_float(hp01 << 16);
            float hy = __uint_as_float(hp01 & 0xFFFF0000u);
            float hz = __uint_as_float(hp23 << 16);
            float hw = __uint_as_float(hp23 & 0xFFFF0000u);
            uint32_t lp01 = pack_bf2(v.x - hx, v.y - hy);
            uint32_t lp23 = pack_bf2(v.z - hz, v.w - hw);
            int ad = kr * SB_STRIDE + nq * 2;
            *reinterpret_cast<uint2*>(smem + OFF_B_HI + ad) = make_uint2(hp01, hp23);
            *reinterpret_cast<uint2*>(smem + OFF_B_LO + ad) = make_uint2(lp01, lp23);
        }
    };

    float acc[2][8][4];
    #pragma unroll
    for (int mt = 0; mt < 2; mt++)
        #pragma unroll
        for (int nt = 0; nt < 8; nt++)
            #pragma unroll
            for (int q = 0; q < 4; q++) acc[mt][nt][q] = 0.f;

    const int nch = K >> 5;
    loadA(0); loadB(0);

    for (int ch = 0; ch < nch; ch++) {
        storeAB();
        __syncthreads();
        if (ch + 1 < nch) { loadA((ch + 1) << 5); loadB((ch + 1) << 5); }

        #pragma unroll
        for (int kk = 0; kk < 32; kk += 16) {
            uint32_t ahi[2][4], alo[2][4];
            #pragma unroll
            for (int mt = 0; mt < 2; mt++) {
                int row = wm + mt * 16 + (lane & 15);
                int col = kk + ((lane >> 4) << 3);
                uint32_t aadr = sb + OFF_A_HI + row * SA_STRIDE + col * 2;
                LDSM4(ahi[mt], aadr);
                LDSM4(alo[mt], aadr + (OFF_A_LO - OFF_A_HI));
            }
            #pragma unroll
            for (int g = 0; g < 4; g++) {
                int krow = kk + ((lane >> 3) & 1) * 8 + (lane & 7);
                int ncol = wn + g * 16 + ((lane >> 4) << 3);
                uint32_t badr = sb + OFF_B_HI + krow * SB_STRIDE + ncol * 2;
                uint32_t bh[4], bl[4];
                LDSM4T(bh, badr);
                LDSM4T(bl, badr + (OFF_B_LO - OFF_B_HI));
                #pragma unroll
                for (int half = 0; half < 2; half++) {
                    int nt = g * 2 + half;
                    #pragma unroll
                    for (int mt = 0; mt < 2; mt++) {
                        MMA16816(acc[mt][nt], ahi[mt], bh + 2 * half);
                        MMA16816(acc[mt][nt], ahi[mt], bl + 2 * half);
                        MMA16816(acc[mt][nt], alo[mt], bh + 2 * half);
                    }
                }
            }
        }
        __syncthreads();
    }

    // ---- epilogue ----
    const int g4 = lane >> 2;
    const int t4 = lane & 3;
    #pragma unroll
    for (int mt = 0; mt < 2; mt++) {
        #pragma unroll
        for (int half = 0; half < 2; half++) {
            int gr = rowBase + wm + mt * 16 + g4 + half * 8;
            if (gr >= M) continue;
            #pragma unroll
            for (int nt = 0; nt < 8; nt++) {
                int cl = wn + nt * 8 + t4 * 2;
                int gc = colBase + cl;
                float v0 = acc[mt][nt][half * 2]     + bias_s[cl];
                float v1 = acc[mt][nt][half * 2 + 1] + bias_s[cl + 1];
                if (RELU) { v0 = fmaxf(v0, 0.f); v1 = fmaxf(v1, 0.f); }
                if (gc + 1 < Nc) {
                    if (ADDRES) {
                        float2 rr = *reinterpret_cast<const float2*>(&Res[(size_t)gr * Nc + gc]);
                        v0 += rr.x; v1 += rr.y;
                    }
                    *reinterpret_cast<float2*>(&C[(size_t)gr * Nc + gc]) = make_float2(v0, v1);
                } else if (gc < Nc) {
                    if (ADDRES) v0 += Res[(size_t)gr * Nc + gc];
                    C[(size_t)gr * Nc + gc] = v0;
                }
            }
        }
    }
}

// ---------------- launch ----------------------------------------------------
extern "C" void kernel_launch(void* const* d_in, const int* in_sizes, int n_in,
                              void* d_out, int out_size) {
    const float* x      = (const float*)d_in[0];
    const int*   src    = (const int*)  d_in[1];
    const int*   dst    = (const int*)  d_in[2];
    const float* self_w = (const float*)d_in[3];
    const float* ppi_w  = (const float*)d_in[4];
    const float* W_in   = (const float*)d_in[5];
    const float* b_in   = (const float*)d_in[6];
    const float* W1     = (const float*)d_in[7];
    const float* b1     = (const float*)d_in[8];
    const float* W2     = (const float*)d_in[9];
    const float* b2     = (const float*)d_in[10];
    const float* W_out  = (const float*)d_in[11];
    const float* b_out  = (const float*)d_in[12];
    float* out = (float*)d_out;
    const int E = in_sizes[1];

    float *ha, *hb, *agg, *res;
    cudaGetSymbolAddress((void**)&ha,  g_ha);
    cudaGetSymbolAddress((void**)&hb,  g_hb);
    cudaGetSymbolAddress((void**)&agg, g_agg);
    cudaGetSymbolAddress((void**)&res, g_res);

    const dim3 blk(256);
    const dim3 g_h((NNODES + 127) / 128, 1);
    const dim3 g_o((NNODES + 127) / 128, (NLAB + 127) / 128);
    const int agg_blocks = (NNODES * 32 + 255) / 256;

    // h = relu(x @ W_in + b_in)   (independent of CSR build; launch first)
    mma_gemm<true, false><<<g_h, blk>>>(x, W_in, b_in, nullptr, ha, NNODES, DIN, DH);

    // CSR by dst (rebuilt every call; g_cnt is zero on entry, re-zeroed in scanC)
    hist_kernel<<<(E + 255) / 256, 256>>>(dst, E);
    scanA_kernel<<<NSCANB, 256>>>();
    scanB_kernel<<<1, 256>>>();
    scanC_kernel<<<NSCANB, 256>>>();
    scatter_kernel<<<(E + 255) / 256, 256>>>(src, dst, self_w, ppi_w, E);

    // layer 1
    aggregate_kernel<<<agg_blocks, blk>>>(ha);
    mma_gemm<true, true><<<g_h, blk>>>(agg, W1, b1, res, hb, NNODES, DH, DH);
    // layer 2
    aggregate_kernel<<<agg_blocks, blk>>>(hb);
    mma_gemm<true, true><<<g_h, blk>>>(agg, W2, b2, res, ha, NNODES, DH, DH);
    // out = h @ W_out + b_out
    mma_gemm<false, false><<<g_o, blk>>>(ha, W_out, b_out, nullptr, out, NNODES, DH, NLAB);
}